// round 11
// baseline (speedup 1.0000x reference)
#include <cuda_runtime.h>
#include <cuda_bf16.h>
#include <cuda_fp8.h>

#define NN 8192
#define TEMPER 0.2f

// Scratch (static __device__ arrays per harness rules)
static __device__ unsigned char g_Q8[(size_t)NN * NN];  // 64 MB fp8 e4m3 Q
static __device__ float g_slice[10][2][NN];             // per-iteration col accumulators
static __device__ float g_V[NN];
static __device__ float g_U[NN];
static __device__ double g_sum;
static __device__ double g_sumsq;
static __device__ float g_kscale;
static __device__ unsigned int g_redCount;
static __device__ unsigned int g_cnt[10];               // per-iteration completion counters

// ---------------------------------------------------------------- helpers
__device__ __forceinline__ float2 f8x2_to_f2(unsigned int s) {
    __half2_raw hr = __nv_cvt_fp8x2_to_halfraw2((__nv_fp8x2_storage_t)s, __NV_E4M3);
    return __half22float2(*reinterpret_cast<__half2*>(&hr));
}

// Tail: last finishing block of a col-accumulating kernel computes g_V = B/(s0+s1).
// Call from ALL threads of the block (block-wide participation via shared flag).
__device__ __forceinline__ void v_finalize_tail(const float* __restrict__ B,
                                                int slot, unsigned int totalBlocks) {
    __shared__ int isLast;
    if (threadIdx.x == 0) {
        __threadfence();
        unsigned int d = atomicAdd(&g_cnt[slot], 1u);
        isLast = (d == totalBlocks - 1u) ? 1 : 0;
    }
    __syncthreads();
    if (isLast) {
        int tid = threadIdx.x;
        const float4* s0 = reinterpret_cast<const float4*>(g_slice[slot][0]);
        const float4* s1 = reinterpret_cast<const float4*>(g_slice[slot][1]);
        const float4* b4 = reinterpret_cast<const float4*>(B);
        float4* v4 = reinterpret_cast<float4*>(g_V);
#pragma unroll
        for (int i = 0; i < 8; ++i) {
            int idx = tid + i * 256;
            float4 a = s0[idx];
            float4 b = s1[idx];
            float4 w = b4[idx];
            float4 v;
            v.x = w.x / (a.x + b.x);
            v.y = w.y / (a.y + b.y);
            v.z = w.z / (a.z + b.z);
            v.w = w.w / (a.w + b.w);
            v4[idx] = v;
        }
        __threadfence();
    }
}

// Copy g_V into SMEM (32 KB), 256 threads, conflict-free
__device__ __forceinline__ void copy_V_smem(float* sV) {
    int tid = threadIdx.x;
#pragma unroll
    for (int i = 0; i < 8; ++i)
        reinterpret_cast<float4*>(sV)[tid + i * 256] =
            reinterpret_cast<const float4*>(g_V)[tid + i * 256];
}

// ---------------------------------------------------------------- init: zero slices + counters
__global__ void k_init() {
    int i = blockIdx.x * blockDim.x + threadIdx.x;
    float* p = &g_slice[0][0][0];
    int total = 10 * 2 * NN;
    for (int j = i; j < total; j += gridDim.x * blockDim.x) p[j] = 0.0f;
    if (i < 10) g_cnt[i] = 0u;
    if (i == 0) {
        g_sum = 0.0;
        g_sumsq = 0.0;
        g_redCount = 0u;
    }
}

// ---------------------------------------------------------------- reduce: sum / sumsq + fused scalar finalize
__global__ void __launch_bounds__(256) k_reduce(const float* __restrict__ c) {
    const size_t total4 = (size_t)NN * NN / 4;
    const size_t stride = (size_t)gridDim.x * blockDim.x;
    double s = 0.0, ss = 0.0;
    for (size_t i = (size_t)blockIdx.x * blockDim.x + threadIdx.x; i < total4; i += stride) {
        float4 v = reinterpret_cast<const float4*>(c)[i];
        float cs  = (v.x + v.y) + (v.z + v.w);
        float css = fmaf(v.x, v.x, fmaf(v.y, v.y, fmaf(v.z, v.z, v.w * v.w)));
        s  += (double)cs;
        ss += (double)css;
    }
    for (int o = 16; o > 0; o >>= 1) {
        s  += __shfl_down_sync(0xffffffffu, s, o);
        ss += __shfl_down_sync(0xffffffffu, ss, o);
    }
    __shared__ double sh_s[8], sh_ss[8];
    int warp = threadIdx.x >> 5, lane = threadIdx.x & 31;
    if (lane == 0) { sh_s[warp] = s; sh_ss[warp] = ss; }
    __syncthreads();
    if (threadIdx.x < 8) {
        s = sh_s[threadIdx.x]; ss = sh_ss[threadIdx.x];
        for (int o = 4; o > 0; o >>= 1) {
            s  += __shfl_down_sync(0xffu, s, o);
            ss += __shfl_down_sync(0xffu, ss, o);
        }
        if (threadIdx.x == 0) {
            atomicAdd(&g_sum, s);
            atomicAdd(&g_sumsq, ss);
            __threadfence();
            unsigned int done = atomicAdd(&g_redCount, 1u);
            if (done == gridDim.x - 1) {
                double n = (double)NN * (double)NN;
                double S  = *(volatile double*)&g_sum;
                double SS = *(volatile double*)&g_sumsq;
                double var = (SS - S * S / n) / (n - 1.0);
                g_kscale = 1.0f / ((float)sqrt(var) * TEMPER);
            }
        }
    }
}

// ---------------------------------------------------------------- build Q8 (fp8) + exact colsum -> slice[0]; tail computes V1
__global__ void __launch_bounds__(256) k_build8(const float* __restrict__ c,
                                                const float* __restrict__ B) {
    const float kk = g_kscale;
    int col0 = (blockIdx.x * 256 + threadIdx.x) * 4;
    int row0 = blockIdx.y * 64;
    float a0 = 0.f, a1 = 0.f, a2 = 0.f, a3 = 0.f;
    for (int r = 0; r < 64; ++r) {
        size_t base = (size_t)(row0 + r) * NN + col0;
        float4 v = *reinterpret_cast<const float4*>(c + base);
        float q0 = __expf(-v.x * kk);
        float q1 = __expf(-v.y * kk);
        float q2 = __expf(-v.z * kk);
        float q3 = __expf(-v.w * kk);
        a0 += q0; a1 += q1; a2 += q2; a3 += q3;
        float2 p0; p0.x = q0; p0.y = q1;
        float2 p1; p1.x = q2; p1.y = q3;
        unsigned int lo = __nv_cvt_float2_to_fp8x2(p0, __NV_SATFINITE, __NV_E4M3);
        unsigned int hi = __nv_cvt_float2_to_fp8x2(p1, __NV_SATFINITE, __NV_E4M3);
        *reinterpret_cast<unsigned int*>(g_Q8 + base) = (hi << 16) | (lo & 0xffffu);
    }
    float* ca = g_slice[0][blockIdx.y & 1];
    atomicAdd(&ca[col0 + 0], a0);
    atomicAdd(&ca[col0 + 1], a1);
    atomicAdd(&ca[col0 + 2], a2);
    atomicAdd(&ca[col0 + 3], a3);
    v_finalize_tail(B, 0, gridDim.x * gridDim.y);
}

// ---------------------------------------------------------------- U = A / (Q8 V)
// 1024 blocks x 256 threads; warp per row; DOUBLE-BUFFERED batch-8 loads
__global__ void __launch_bounds__(256) k_rowmv8(const float* __restrict__ A) {
    __shared__ float sV[NN];
    copy_V_smem(sV);
    __syncthreads();
    int tid = threadIdx.x, warp = tid >> 5, lane = tid & 31;
    int row = blockIdx.x * 8 + warp;
    const unsigned int* q = reinterpret_cast<const unsigned int*>(g_Q8 + (size_t)row * NN);
    const float4* v4 = reinterpret_cast<const float4*>(sV);
    unsigned int buf[2][8];
#pragma unroll
    for (int u = 0; u < 8; ++u) buf[0][u] = q[lane + u * 32];
    float acc = 0.f;
#pragma unroll
    for (int s = 0; s < 64; s += 8) {
        const int p = (s >> 3) & 1;
        if (s + 8 < 64) {
#pragma unroll
            for (int u = 0; u < 8; ++u) buf[p ^ 1][u] = q[lane + (s + 8 + u) * 32];
        }
#pragma unroll
        for (int u = 0; u < 8; ++u) {
            float4 v = v4[lane + (s + u) * 32];
            float2 lo = f8x2_to_f2(buf[p][u] & 0xffffu);
            float2 hi = f8x2_to_f2(buf[p][u] >> 16);
            acc = fmaf(lo.x, v.x, acc);
            acc = fmaf(lo.y, v.y, acc);
            acc = fmaf(hi.x, v.z, acc);
            acc = fmaf(hi.y, v.w, acc);
        }
    }
    for (int o = 16; o > 0; o >>= 1)
        acc += __shfl_down_sync(0xffffffffu, acc, o);
    if (lane == 0) g_U[row] = __ldg(A + row) / acc;
}

// ---------------------------------------------------------------- slice[it] += Q8^T U; tail computes V_{it+1}
// 1024 blocks: 128 row-chunks x 8 col-chunks; 4 cols/thread; double-buffered rows
__global__ void __launch_bounds__(256) k_colmv8(const float* __restrict__ B, int it) {
    __shared__ float sU[64];
    int tid = threadIdx.x;
    int rb = blockIdx.x >> 3;
    int col0 = (blockIdx.x & 7) * 1024 + tid * 4;
    int row0 = rb * 64;
    if (tid < 64) sU[tid] = g_U[row0 + tid];
    __syncthreads();
    const unsigned int* qp =
        reinterpret_cast<const unsigned int*>(g_Q8 + (size_t)row0 * NN + col0);
    unsigned int w[2][8];
#pragma unroll
    for (int u = 0; u < 8; ++u) w[0][u] = qp[(size_t)u * (NN / 4)];
    float a0 = 0.f, a1 = 0.f, a2 = 0.f, a3 = 0.f;
#pragma unroll
    for (int r = 0; r < 64; r += 8) {
        const int p = (r >> 3) & 1;
        if (r + 8 < 64) {
#pragma unroll
            for (int u = 0; u < 8; ++u) w[p ^ 1][u] = qp[(size_t)(r + 8 + u) * (NN / 4)];
        }
#pragma unroll
        for (int u = 0; u < 8; ++u) {
            float uu = sU[r + u];
            float2 lo = f8x2_to_f2(w[p][u] & 0xffffu);
            float2 hi = f8x2_to_f2(w[p][u] >> 16);
            a0 = fmaf(lo.x, uu, a0);
            a1 = fmaf(lo.y, uu, a1);
            a2 = fmaf(hi.x, uu, a2);
            a3 = fmaf(hi.y, uu, a3);
        }
    }
    float* ca = g_slice[it][rb & 1];
    atomicAdd(&ca[col0 + 0], a0);
    atomicAdd(&ca[col0 + 1], a1);
    atomicAdd(&ca[col0 + 2], a2);
    atomicAdd(&ca[col0 + 3], a3);
    v_finalize_tail(B, it, gridDim.x);
}

// ---------------------------------------------------------------- exact colmv (V10): slice[9] += Q^T U; tail computes V10
__global__ void __launch_bounds__(256) k_colmv_exact(const float* __restrict__ c,
                                                     const float* __restrict__ B) {
    __shared__ float sU[64];
    int tid = threadIdx.x;
    int rb = blockIdx.x >> 3;
    int col0 = (blockIdx.x & 7) * 1024 + tid * 4;
    int row0 = rb * 64;
    if (tid < 64) sU[tid] = g_U[row0 + tid];
    __syncthreads();
    const float kk = g_kscale;
    const float* cp = c + (size_t)row0 * NN + col0;
    float a0 = 0.f, a1 = 0.f, a2 = 0.f, a3 = 0.f;
#pragma unroll 4
    for (int r = 0; r < 64; ++r) {
        float4 v = *reinterpret_cast<const float4*>(cp + (size_t)r * NN);
        float u = sU[r];
        a0 = fmaf(__expf(-v.x * kk), u, a0);
        a1 = fmaf(__expf(-v.y * kk), u, a1);
        a2 = fmaf(__expf(-v.z * kk), u, a2);
        a3 = fmaf(__expf(-v.w * kk), u, a3);
    }
    float* ca = g_slice[9][rb & 1];
    atomicAdd(&ca[col0 + 0], a0);
    atomicAdd(&ca[col0 + 1], a1);
    atomicAdd(&ca[col0 + 2], a2);
    atomicAdd(&ca[col0 + 3], a3);
    v_finalize_tail(B, 9, gridDim.x);
}

// ---------------------------------------------------------------- final: exact Q, fused U10, write T (V10 in g_V)
__global__ void __launch_bounds__(256) k_final(const float* __restrict__ c,
                                               const float* __restrict__ A,
                                               float* __restrict__ out) {
    __shared__ float sV[NN];
    __shared__ float sred[8];
    __shared__ float sbc;
    int tid = threadIdx.x;
    copy_V_smem(sV);
    __syncthreads();
    const float kk = g_kscale;
    for (int row = blockIdx.x; row < NN; row += gridDim.x) {
        const float4* crow = reinterpret_cast<const float4*>(c + (size_t)row * NN);
        float4 qv[8];
        float s = 0.f;
#pragma unroll
        for (int k = 0; k < 8; ++k) {
            int j = tid * 4 + k * 1024;
            float4 v  = crow[tid + k * 256];
            float4 vv = *reinterpret_cast<const float4*>(sV + j);
            float q0 = __expf(-v.x * kk) * vv.x;
            float q1 = __expf(-v.y * kk) * vv.y;
            float q2 = __expf(-v.z * kk) * vv.z;
            float q3 = __expf(-v.w * kk) * vv.w;
            qv[k].x = q0; qv[k].y = q1; qv[k].z = q2; qv[k].w = q3;
            s += (q0 + q1) + (q2 + q3);
        }
        for (int o = 16; o > 0; o >>= 1)
            s += __shfl_down_sync(0xffffffffu, s, o);
        if ((tid & 31) == 0) sred[tid >> 5] = s;
        __syncthreads();
        if (tid < 32) {
            float t = (tid < 8) ? sred[tid] : 0.f;
            for (int o = 4; o > 0; o >>= 1)
                t += __shfl_down_sync(0xffffffffu, t, o);
            if (tid == 0) sbc = __ldg(A + row) / t;
        }
        __syncthreads();
        float scale = sbc;
        float4* orow = reinterpret_cast<float4*>(out + (size_t)row * NN);
#pragma unroll
        for (int k = 0; k < 8; ++k) {
            float4 w = qv[k];
            w.x *= scale; w.y *= scale; w.z *= scale; w.w *= scale;
            orow[tid + k * 256] = w;
        }
        __syncthreads();
    }
}

// ---------------------------------------------------------------- launch
extern "C" void kernel_launch(void* const* d_in, const int* in_sizes, int n_in,
                              void* d_out, int out_size) {
    const float* cdist = (const float*)d_in[0];
    const float* A     = (const float*)d_in[1];
    const float* B     = (const float*)d_in[2];
    float* out = (float*)d_out;

    k_init<<<64, 256>>>();                       // zero slices + counters
    k_reduce<<<1184, 256>>>(cdist);              // sum/sumsq + fused kscale
    k_build8<<<dim3(8, 128), 256>>>(cdist, B);   // Q8, colsum -> slice[0]; tail -> V1
    for (int it = 1; it <= 8; ++it) {
        k_rowmv8<<<1024, 256>>>(A);              // U_it = A/(Q8 V)  (V in g_V)
        k_colmv8<<<1024, 256>>>(B, it);          // slice[it] = Q8^T U_it; tail -> V_{it+1}
    }
    k_rowmv8<<<1024, 256>>>(A);                  // U9
    k_colmv_exact<<<1024, 256>>>(cdist, B);      // slice[9] = Q^T U9; tail -> V10
    // U10 fused into output: exact fp32 Q, V10 in g_V, T out
    k_final<<<444, 256>>>(cdist, A, out);
}

// round 13
// speedup vs baseline: 1.0376x; 1.0376x over previous
#include <cuda_runtime.h>
#include <cuda_bf16.h>
#include <cuda_fp8.h>

#define NN 8192
#define TEMPER 0.2f

// Scratch (static __device__ arrays per harness rules)
static __device__ unsigned char g_Q8[(size_t)NN * NN];  // 64 MB fp8 e4m3 Q
static __device__ float g_slice[10][2][NN];             // per-iteration col accumulators
static __device__ float g_V[NN];
static __device__ float g_U[NN];
static __device__ double g_sum;
static __device__ double g_sumsq;
static __device__ float g_kscale;
static __device__ unsigned int g_redCount;
static __device__ unsigned int g_cnt[10];               // per-iteration completion counters

// ---------------------------------------------------------------- helpers
__device__ __forceinline__ float2 f8x2_to_f2(unsigned int s) {
    __half2_raw hr = __nv_cvt_fp8x2_to_halfraw2((__nv_fp8x2_storage_t)s, __NV_E4M3);
    return __half22float2(*reinterpret_cast<__half2*>(&hr));
}

// Tail: last finishing block computes g_V = B/(s0+s1). Call from ALL threads.
__device__ __forceinline__ void v_finalize_tail(const float* __restrict__ B,
                                                int slot, unsigned int totalBlocks) {
    __shared__ int isLast;
    if (threadIdx.x == 0) {
        __threadfence();
        unsigned int d = atomicAdd(&g_cnt[slot], 1u);
        isLast = (d == totalBlocks - 1u) ? 1 : 0;
    }
    __syncthreads();
    if (isLast) {
        int tid = threadIdx.x;
        const float4* s0 = reinterpret_cast<const float4*>(g_slice[slot][0]);
        const float4* s1 = reinterpret_cast<const float4*>(g_slice[slot][1]);
        const float4* b4 = reinterpret_cast<const float4*>(B);
        float4* v4 = reinterpret_cast<float4*>(g_V);
#pragma unroll
        for (int i = 0; i < 8; ++i) {
            int idx = tid + i * 256;
            float4 a = s0[idx];
            float4 b = s1[idx];
            float4 w = b4[idx];
            float4 v;
            v.x = w.x / (a.x + b.x);
            v.y = w.y / (a.y + b.y);
            v.z = w.z / (a.z + b.z);
            v.w = w.w / (a.w + b.w);
            v4[idx] = v;
        }
        __threadfence();
    }
}

// Copy g_V into SMEM (32 KB), 256 threads, conflict-free
__device__ __forceinline__ void copy_V_smem(float* sV) {
    int tid = threadIdx.x;
#pragma unroll
    for (int i = 0; i < 8; ++i)
        reinterpret_cast<float4*>(sV)[tid + i * 256] =
            reinterpret_cast<const float4*>(g_V)[tid + i * 256];
}

// ---------------------------------------------------------------- init: zero slices + counters
__global__ void k_init() {
    int i = blockIdx.x * blockDim.x + threadIdx.x;
    float* p = &g_slice[0][0][0];
    int total = 10 * 2 * NN;
    for (int j = i; j < total; j += gridDim.x * blockDim.x) p[j] = 0.0f;
    if (i < 10) g_cnt[i] = 0u;
    if (i == 0) {
        g_sum = 0.0;
        g_sumsq = 0.0;
        g_redCount = 0u;
    }
}

// ---------------------------------------------------------------- reduce: sum / sumsq + fused scalar finalize
__global__ void __launch_bounds__(256) k_reduce(const float* __restrict__ c) {
    const size_t total4 = (size_t)NN * NN / 4;
    const size_t stride = (size_t)gridDim.x * blockDim.x;
    double s = 0.0, ss = 0.0;
    for (size_t i = (size_t)blockIdx.x * blockDim.x + threadIdx.x; i < total4; i += stride) {
        float4 v = reinterpret_cast<const float4*>(c)[i];
        float cs  = (v.x + v.y) + (v.z + v.w);
        float css = fmaf(v.x, v.x, fmaf(v.y, v.y, fmaf(v.z, v.z, v.w * v.w)));
        s  += (double)cs;
        ss += (double)css;
    }
    for (int o = 16; o > 0; o >>= 1) {
        s  += __shfl_down_sync(0xffffffffu, s, o);
        ss += __shfl_down_sync(0xffffffffu, ss, o);
    }
    __shared__ double sh_s[8], sh_ss[8];
    int warp = threadIdx.x >> 5, lane = threadIdx.x & 31;
    if (lane == 0) { sh_s[warp] = s; sh_ss[warp] = ss; }
    __syncthreads();
    if (threadIdx.x < 8) {
        s = sh_s[threadIdx.x]; ss = sh_ss[threadIdx.x];
        for (int o = 4; o > 0; o >>= 1) {
            s  += __shfl_down_sync(0xffu, s, o);
            ss += __shfl_down_sync(0xffu, ss, o);
        }
        if (threadIdx.x == 0) {
            atomicAdd(&g_sum, s);
            atomicAdd(&g_sumsq, ss);
            __threadfence();
            unsigned int done = atomicAdd(&g_redCount, 1u);
            if (done == gridDim.x - 1) {
                double n = (double)NN * (double)NN;
                double S  = *(volatile double*)&g_sum;
                double SS = *(volatile double*)&g_sumsq;
                double var = (SS - S * S / n) / (n - 1.0);
                g_kscale = 1.0f / ((float)sqrt(var) * TEMPER);
            }
        }
    }
}

// ---------------------------------------------------------------- build Q8 (fp8) + exact colsum -> slice[0]; tail -> V1
__global__ void __launch_bounds__(256) k_build8(const float* __restrict__ c,
                                                const float* __restrict__ B) {
    const float kk = g_kscale;
    int col0 = (blockIdx.x * 256 + threadIdx.x) * 4;
    int row0 = blockIdx.y * 64;
    float a0 = 0.f, a1 = 0.f, a2 = 0.f, a3 = 0.f;
    for (int r = 0; r < 64; ++r) {
        size_t base = (size_t)(row0 + r) * NN + col0;
        float4 v = *reinterpret_cast<const float4*>(c + base);
        float q0 = __expf(-v.x * kk);
        float q1 = __expf(-v.y * kk);
        float q2 = __expf(-v.z * kk);
        float q3 = __expf(-v.w * kk);
        a0 += q0; a1 += q1; a2 += q2; a3 += q3;
        float2 p0; p0.x = q0; p0.y = q1;
        float2 p1; p1.x = q2; p1.y = q3;
        unsigned int lo = __nv_cvt_float2_to_fp8x2(p0, __NV_SATFINITE, __NV_E4M3);
        unsigned int hi = __nv_cvt_float2_to_fp8x2(p1, __NV_SATFINITE, __NV_E4M3);
        *reinterpret_cast<unsigned int*>(g_Q8 + base) = (hi << 16) | (lo & 0xffffu);
    }
    float* ca = g_slice[0][blockIdx.y & 1];
    atomicAdd(&ca[col0 + 0], a0);
    atomicAdd(&ca[col0 + 1], a1);
    atomicAdd(&ca[col0 + 2], a2);
    atomicAdd(&ca[col0 + 3], a3);
    v_finalize_tail(B, 0, gridDim.x * gridDim.y);
}

// ---------------------------------------------------------------- U = A / (Q8 V)
// 512 blocks x 256 threads; warp = 2 rows SHARING V reads; double-buffered 4-step batches
__global__ void __launch_bounds__(256) k_rowmv8(const float* __restrict__ A) {
    __shared__ float sV[NN];
    copy_V_smem(sV);
    __syncthreads();
    int tid = threadIdx.x, warp = tid >> 5, lane = tid & 31;
    int row0 = blockIdx.x * 16 + warp * 2;
    const unsigned int* q0 = reinterpret_cast<const unsigned int*>(g_Q8 + (size_t)row0 * NN);
    const unsigned int* q1 = reinterpret_cast<const unsigned int*>(g_Q8 + (size_t)(row0 + 1) * NN);
    const float4* v4 = reinterpret_cast<const float4*>(sV);
    unsigned int bufa[2][4], bufb[2][4];
#pragma unroll
    for (int u = 0; u < 4; ++u) {
        bufa[0][u] = q0[lane + u * 32];
        bufb[0][u] = q1[lane + u * 32];
    }
    float acc0 = 0.f, acc1 = 0.f;
#pragma unroll
    for (int s = 0; s < 64; s += 4) {
        const int p = (s >> 2) & 1;
        if (s + 4 < 64) {
#pragma unroll
            for (int u = 0; u < 4; ++u) {
                bufa[p ^ 1][u] = q0[lane + (s + 4 + u) * 32];
                bufb[p ^ 1][u] = q1[lane + (s + 4 + u) * 32];
            }
        }
#pragma unroll
        for (int u = 0; u < 4; ++u) {
            float4 v = v4[lane + (s + u) * 32];
            float2 lo = f8x2_to_f2(bufa[p][u] & 0xffffu);
            float2 hi = f8x2_to_f2(bufa[p][u] >> 16);
            acc0 = fmaf(lo.x, v.x, acc0);
            acc0 = fmaf(lo.y, v.y, acc0);
            acc0 = fmaf(hi.x, v.z, acc0);
            acc0 = fmaf(hi.y, v.w, acc0);
            float2 lo1 = f8x2_to_f2(bufb[p][u] & 0xffffu);
            float2 hi1 = f8x2_to_f2(bufb[p][u] >> 16);
            acc1 = fmaf(lo1.x, v.x, acc1);
            acc1 = fmaf(lo1.y, v.y, acc1);
            acc1 = fmaf(hi1.x, v.z, acc1);
            acc1 = fmaf(hi1.y, v.w, acc1);
        }
    }
    for (int o = 16; o > 0; o >>= 1) {
        acc0 += __shfl_down_sync(0xffffffffu, acc0, o);
        acc1 += __shfl_down_sync(0xffffffffu, acc1, o);
    }
    if (lane == 0) {
        g_U[row0]     = __ldg(A + row0) / acc0;
        g_U[row0 + 1] = __ldg(A + row0 + 1) / acc1;
    }
}

// ---------------------------------------------------------------- slice[it] += Q8^T U; tail -> V_{it+1}
// 1024 blocks: 128 row-chunks x 8 col-chunks; 4 cols/thread; double-buffered rows
__global__ void __launch_bounds__(256) k_colmv8(const float* __restrict__ B, int it) {
    __shared__ float sU[64];
    int tid = threadIdx.x;
    int rb = blockIdx.x >> 3;
    int col0 = (blockIdx.x & 7) * 1024 + tid * 4;
    int row0 = rb * 64;
    if (tid < 64) sU[tid] = g_U[row0 + tid];
    __syncthreads();
    const unsigned int* qp =
        reinterpret_cast<const unsigned int*>(g_Q8 + (size_t)row0 * NN + col0);
    unsigned int w[2][8];
#pragma unroll
    for (int u = 0; u < 8; ++u) w[0][u] = qp[(size_t)u * (NN / 4)];
    float a0 = 0.f, a1 = 0.f, a2 = 0.f, a3 = 0.f;
#pragma unroll
    for (int r = 0; r < 64; r += 8) {
        const int p = (r >> 3) & 1;
        if (r + 8 < 64) {
#pragma unroll
            for (int u = 0; u < 8; ++u) w[p ^ 1][u] = qp[(size_t)(r + 8 + u) * (NN / 4)];
        }
#pragma unroll
        for (int u = 0; u < 8; ++u) {
            float uu = sU[r + u];
            float2 lo = f8x2_to_f2(w[p][u] & 0xffffu);
            float2 hi = f8x2_to_f2(w[p][u] >> 16);
            a0 = fmaf(lo.x, uu, a0);
            a1 = fmaf(lo.y, uu, a1);
            a2 = fmaf(hi.x, uu, a2);
            a3 = fmaf(hi.y, uu, a3);
        }
    }
    float* ca = g_slice[it][rb & 1];
    atomicAdd(&ca[col0 + 0], a0);
    atomicAdd(&ca[col0 + 1], a1);
    atomicAdd(&ca[col0 + 2], a2);
    atomicAdd(&ca[col0 + 3], a3);
    v_finalize_tail(B, it, gridDim.x);
}

// ---------------------------------------------------------------- exact colmv (V10): slice[9] += Q^T U; tail -> V10
__global__ void __launch_bounds__(256) k_colmv_exact(const float* __restrict__ c,
                                                     const float* __restrict__ B) {
    __shared__ float sU[64];
    int tid = threadIdx.x;
    int rb = blockIdx.x >> 3;
    int col0 = (blockIdx.x & 7) * 1024 + tid * 4;
    int row0 = rb * 64;
    if (tid < 64) sU[tid] = g_U[row0 + tid];
    __syncthreads();
    const float kk = g_kscale;
    const float* cp = c + (size_t)row0 * NN + col0;
    float a0 = 0.f, a1 = 0.f, a2 = 0.f, a3 = 0.f;
#pragma unroll 4
    for (int r = 0; r < 64; ++r) {
        float4 v = *reinterpret_cast<const float4*>(cp + (size_t)r * NN);
        float u = sU[r];
        a0 = fmaf(__expf(-v.x * kk), u, a0);
        a1 = fmaf(__expf(-v.y * kk), u, a1);
        a2 = fmaf(__expf(-v.z * kk), u, a2);
        a3 = fmaf(__expf(-v.w * kk), u, a3);
    }
    float* ca = g_slice[9][rb & 1];
    atomicAdd(&ca[col0 + 0], a0);
    atomicAdd(&ca[col0 + 1], a1);
    atomicAdd(&ca[col0 + 2], a2);
    atomicAdd(&ca[col0 + 3], a3);
    v_finalize_tail(B, 9, gridDim.x);
}

// ---------------------------------------------------------------- final: exact Q, fused U10, write T (V10 in g_V)
__global__ void __launch_bounds__(256) k_final(const float* __restrict__ c,
                                               const float* __restrict__ A,
                                               float* __restrict__ out) {
    __shared__ float sV[NN];
    __shared__ float sred[8];
    __shared__ float sbc;
    int tid = threadIdx.x;
    copy_V_smem(sV);
    __syncthreads();
    const float kk = g_kscale;
    for (int row = blockIdx.x; row < NN; row += gridDim.x) {
        const float4* crow = reinterpret_cast<const float4*>(c + (size_t)row * NN);
        float4 qv[8];
        float s = 0.f;
#pragma unroll
        for (int k = 0; k < 8; ++k) {
            int j = tid * 4 + k * 1024;
            float4 v  = crow[tid + k * 256];
            float4 vv = *reinterpret_cast<const float4*>(sV + j);
            float q0 = __expf(-v.x * kk) * vv.x;
            float q1 = __expf(-v.y * kk) * vv.y;
            float q2 = __expf(-v.z * kk) * vv.z;
            float q3 = __expf(-v.w * kk) * vv.w;
            qv[k].x = q0; qv[k].y = q1; qv[k].z = q2; qv[k].w = q3;
            s += (q0 + q1) + (q2 + q3);
        }
        for (int o = 16; o > 0; o >>= 1)
            s += __shfl_down_sync(0xffffffffu, s, o);
        if ((tid & 31) == 0) sred[tid >> 5] = s;
        __syncthreads();
        if (tid < 32) {
            float t = (tid < 8) ? sred[tid] : 0.f;
            for (int o = 4; o > 0; o >>= 1)
                t += __shfl_down_sync(0xffffffffu, t, o);
            if (tid == 0) sbc = __ldg(A + row) / t;
        }
        __syncthreads();
        float scale = sbc;
        float4* orow = reinterpret_cast<float4*>(out + (size_t)row * NN);
#pragma unroll
        for (int k = 0; k < 8; ++k) {
            float4 w = qv[k];
            w.x *= scale; w.y *= scale; w.z *= scale; w.w *= scale;
            orow[tid + k * 256] = w;
        }
        __syncthreads();
    }
}

// ---------------------------------------------------------------- launch
extern "C" void kernel_launch(void* const* d_in, const int* in_sizes, int n_in,
                              void* d_out, int out_size) {
    const float* cdist = (const float*)d_in[0];
    const float* A     = (const float*)d_in[1];
    const float* B     = (const float*)d_in[2];
    float* out = (float*)d_out;

    k_init<<<64, 256>>>();                       // zero slices + counters
    k_reduce<<<1184, 256>>>(cdist);              // sum/sumsq + fused kscale
    k_build8<<<dim3(8, 128), 256>>>(cdist, B);   // Q8, colsum -> slice[0]; tail -> V1
    for (int it = 1; it <= 8; ++it) {
        k_rowmv8<<<512, 256>>>(A);               // U_it = A/(Q8 V)
        k_colmv8<<<1024, 256>>>(B, it);          // slice[it] = Q8^T U_it; tail -> V_{it+1}
    }
    k_rowmv8<<<512, 256>>>(A);                   // U9
    k_colmv_exact<<<1024, 256>>>(cdist, B);      // slice[9] = Q^T U9; tail -> V10
    // U10 fused into output: exact fp32 Q, V10 in g_V, T out
    k_final<<<444, 256>>>(cdist, A, out);
}

// round 15
// speedup vs baseline: 1.0618x; 1.0234x over previous
#include <cuda_runtime.h>
#include <cuda_bf16.h>
#include <cuda_fp8.h>

#define NN 8192
#define TEMPER 0.2f

// Scratch (static __device__ arrays per harness rules)
static __device__ unsigned char g_Q8[(size_t)NN * NN];  // 64 MB fp8 e4m3 Q
static __device__ float g_slice[10][2][NN];             // per-iteration col accumulators
static __device__ float g_Dsl[2][NN];                   // colsum(Q - Q8) residual, sliced
static __device__ float g_V[NN];
static __device__ float g_U[NN];
static __device__ float g_usum[10];                     // sum(U) per iteration
static __device__ double g_sum;
static __device__ double g_sumsq;
static __device__ float g_kscale;
static __device__ unsigned int g_redCount;
static __device__ unsigned int g_cnt[10];               // per-iteration completion counters

// ---------------------------------------------------------------- helpers
__device__ __forceinline__ float2 f8x2_to_f2(unsigned int s) {
    __half2_raw hr = __nv_cvt_fp8x2_to_halfraw2((__nv_fp8x2_storage_t)s, __NV_E4M3);
    return __half22float2(*reinterpret_cast<__half2*>(&hr));
}

// Tail: last finishing block computes g_V = B/(s0+s1+ubar*D). Call from ALL threads.
__device__ __forceinline__ void v_finalize_tail(const float* __restrict__ B,
                                                int slot, unsigned int totalBlocks,
                                                int useCorr) {
    __shared__ int isLast;
    if (threadIdx.x == 0) {
        __threadfence();
        unsigned int d = atomicAdd(&g_cnt[slot], 1u);
        isLast = (d == totalBlocks - 1u) ? 1 : 0;
    }
    __syncthreads();
    if (isLast) {
        int tid = threadIdx.x;
        float ubar = useCorr ? (g_usum[slot] * (1.0f / NN)) : 0.0f;
        const float4* s0 = reinterpret_cast<const float4*>(g_slice[slot][0]);
        const float4* s1 = reinterpret_cast<const float4*>(g_slice[slot][1]);
        const float4* d0 = reinterpret_cast<const float4*>(g_Dsl[0]);
        const float4* d1 = reinterpret_cast<const float4*>(g_Dsl[1]);
        const float4* b4 = reinterpret_cast<const float4*>(B);
        float4* v4 = reinterpret_cast<float4*>(g_V);
#pragma unroll
        for (int i = 0; i < 8; ++i) {
            int idx = tid + i * 256;
            float4 a = s0[idx];
            float4 b = s1[idx];
            float4 da = d0[idx];
            float4 db = d1[idx];
            float4 w = b4[idx];
            float4 v;
            v.x = w.x / (a.x + b.x + ubar * (da.x + db.x));
            v.y = w.y / (a.y + b.y + ubar * (da.y + db.y));
            v.z = w.z / (a.z + b.z + ubar * (da.z + db.z));
            v.w = w.w / (a.w + b.w + ubar * (da.w + db.w));
            v4[idx] = v;
        }
        __threadfence();
    }
}

// Copy g_V into SMEM (32 KB), 256 threads, conflict-free
__device__ __forceinline__ void copy_V_smem(float* sV) {
    int tid = threadIdx.x;
#pragma unroll
    for (int i = 0; i < 8; ++i)
        reinterpret_cast<float4*>(sV)[tid + i * 256] =
            reinterpret_cast<const float4*>(g_V)[tid + i * 256];
}

// ---------------------------------------------------------------- init: zero slices + counters
__global__ void k_init() {
    int i = blockIdx.x * blockDim.x + threadIdx.x;
    float* p = &g_slice[0][0][0];
    int total = 10 * 2 * NN;
    for (int j = i; j < total; j += gridDim.x * blockDim.x) p[j] = 0.0f;
    float* pd = &g_Dsl[0][0];
    for (int j = i; j < 2 * NN; j += gridDim.x * blockDim.x) pd[j] = 0.0f;
    if (i < 10) { g_cnt[i] = 0u; g_usum[i] = 0.0f; }
    if (i == 0) {
        g_sum = 0.0;
        g_sumsq = 0.0;
        g_redCount = 0u;
    }
}

// ---------------------------------------------------------------- reduce: sum / sumsq + fused scalar finalize
__global__ void __launch_bounds__(256) k_reduce(const float* __restrict__ c) {
    const size_t total4 = (size_t)NN * NN / 4;
    const size_t stride = (size_t)gridDim.x * blockDim.x;
    double s = 0.0, ss = 0.0;
    for (size_t i = (size_t)blockIdx.x * blockDim.x + threadIdx.x; i < total4; i += stride) {
        float4 v = reinterpret_cast<const float4*>(c)[i];
        float cs  = (v.x + v.y) + (v.z + v.w);
        float css = fmaf(v.x, v.x, fmaf(v.y, v.y, fmaf(v.z, v.z, v.w * v.w)));
        s  += (double)cs;
        ss += (double)css;
    }
    for (int o = 16; o > 0; o >>= 1) {
        s  += __shfl_down_sync(0xffffffffu, s, o);
        ss += __shfl_down_sync(0xffffffffu, ss, o);
    }
    __shared__ double sh_s[8], sh_ss[8];
    int warp = threadIdx.x >> 5, lane = threadIdx.x & 31;
    if (lane == 0) { sh_s[warp] = s; sh_ss[warp] = ss; }
    __syncthreads();
    if (threadIdx.x < 8) {
        s = sh_s[threadIdx.x]; ss = sh_ss[threadIdx.x];
        for (int o = 4; o > 0; o >>= 1) {
            s  += __shfl_down_sync(0xffu, s, o);
            ss += __shfl_down_sync(0xffu, ss, o);
        }
        if (threadIdx.x == 0) {
            atomicAdd(&g_sum, s);
            atomicAdd(&g_sumsq, ss);
            __threadfence();
            unsigned int done = atomicAdd(&g_redCount, 1u);
            if (done == gridDim.x - 1) {
                double n = (double)NN * (double)NN;
                double S  = *(volatile double*)&g_sum;
                double SS = *(volatile double*)&g_sumsq;
                double var = (SS - S * S / n) / (n - 1.0);
                g_kscale = 1.0f / ((float)sqrt(var) * TEMPER);
            }
        }
    }
}

// ---------------------------------------------------------------- build Q8 + exact colsum -> slice[0]
// also accumulates D = colsum(Q - Q8); tail -> V1 (exact, no corr needed)
__global__ void __launch_bounds__(256) k_build8(const float* __restrict__ c,
                                                const float* __restrict__ B) {
    const float kk = g_kscale;
    int col0 = (blockIdx.x * 256 + threadIdx.x) * 4;
    int row0 = blockIdx.y * 64;
    float a0 = 0.f, a1 = 0.f, a2 = 0.f, a3 = 0.f;
    float e0 = 0.f, e1 = 0.f, e2 = 0.f, e3 = 0.f;
    for (int r = 0; r < 64; ++r) {
        size_t base = (size_t)(row0 + r) * NN + col0;
        float4 v = *reinterpret_cast<const float4*>(c + base);
        float q0 = __expf(-v.x * kk);
        float q1 = __expf(-v.y * kk);
        float q2 = __expf(-v.z * kk);
        float q3 = __expf(-v.w * kk);
        a0 += q0; a1 += q1; a2 += q2; a3 += q3;
        float2 p0; p0.x = q0; p0.y = q1;
        float2 p1; p1.x = q2; p1.y = q3;
        unsigned int lo = __nv_cvt_float2_to_fp8x2(p0, __NV_SATFINITE, __NV_E4M3);
        unsigned int hi = __nv_cvt_float2_to_fp8x2(p1, __NV_SATFINITE, __NV_E4M3);
        // decode-back for residual
        float2 dl = f8x2_to_f2(lo);
        float2 dh = f8x2_to_f2(hi);
        e0 += q0 - dl.x; e1 += q1 - dl.y; e2 += q2 - dh.x; e3 += q3 - dh.y;
        *reinterpret_cast<unsigned int*>(g_Q8 + base) = (hi << 16) | (lo & 0xffffu);
    }
    float* ca = g_slice[0][blockIdx.y & 1];
    atomicAdd(&ca[col0 + 0], a0);
    atomicAdd(&ca[col0 + 1], a1);
    atomicAdd(&ca[col0 + 2], a2);
    atomicAdd(&ca[col0 + 3], a3);
    float* cd = g_Dsl[blockIdx.y & 1];
    atomicAdd(&cd[col0 + 0], e0);
    atomicAdd(&cd[col0 + 1], e1);
    atomicAdd(&cd[col0 + 2], e2);
    atomicAdd(&cd[col0 + 3], e3);
    v_finalize_tail(B, 0, gridDim.x * gridDim.y, 0);
}

// ---------------------------------------------------------------- U = A / (Q8 V)
// 1024 blocks x 256 threads; block = 8 rows; TWO warps per row-pair (col halves)
// warp w: pair=w&3 (rows rowBase+2*pair..+1), half=w>>2 (cols half*4096..+4096)
__global__ void __launch_bounds__(256) k_rowmv8(const float* __restrict__ A, int slot) {
    __shared__ float sV[NN];
    __shared__ float sdot[8][2];
    __shared__ float sUp[4];
    copy_V_smem(sV);
    __syncthreads();
    int tid = threadIdx.x, warp = tid >> 5, lane = tid & 31;
    int pair = warp & 3, half = warp >> 2;
    int rowBase = blockIdx.x * 8;
    int r0 = rowBase + pair * 2;
    const unsigned int* q0 =
        reinterpret_cast<const unsigned int*>(g_Q8 + (size_t)r0 * NN) + half * 1024;
    const unsigned int* q1 =
        reinterpret_cast<const unsigned int*>(g_Q8 + (size_t)(r0 + 1) * NN) + half * 1024;
    const float4* v4 = reinterpret_cast<const float4*>(sV) + half * 1024;
    unsigned int bufa[2][4], bufb[2][4];
#pragma unroll
    for (int u = 0; u < 4; ++u) {
        bufa[0][u] = q0[lane + u * 32];
        bufb[0][u] = q1[lane + u * 32];
    }
    float acc0 = 0.f, acc1 = 0.f;
#pragma unroll
    for (int s = 0; s < 32; s += 4) {
        const int p = (s >> 2) & 1;
        if (s + 4 < 32) {
#pragma unroll
            for (int u = 0; u < 4; ++u) {
                bufa[p ^ 1][u] = q0[lane + (s + 4 + u) * 32];
                bufb[p ^ 1][u] = q1[lane + (s + 4 + u) * 32];
            }
        }
#pragma unroll
        for (int u = 0; u < 4; ++u) {
            float4 v = v4[lane + (s + u) * 32];
            float2 lo = f8x2_to_f2(bufa[p][u] & 0xffffu);
            float2 hi = f8x2_to_f2(bufa[p][u] >> 16);
            acc0 = fmaf(lo.x, v.x, acc0);
            acc0 = fmaf(lo.y, v.y, acc0);
            acc0 = fmaf(hi.x, v.z, acc0);
            acc0 = fmaf(hi.y, v.w, acc0);
            float2 lo1 = f8x2_to_f2(bufb[p][u] & 0xffffu);
            float2 hi1 = f8x2_to_f2(bufb[p][u] >> 16);
            acc1 = fmaf(lo1.x, v.x, acc1);
            acc1 = fmaf(lo1.y, v.y, acc1);
            acc1 = fmaf(hi1.x, v.z, acc1);
            acc1 = fmaf(hi1.y, v.w, acc1);
        }
    }
    for (int o = 16; o > 0; o >>= 1) {
        acc0 += __shfl_down_sync(0xffffffffu, acc0, o);
        acc1 += __shfl_down_sync(0xffffffffu, acc1, o);
    }
    if (lane == 0) { sdot[warp][0] = acc0; sdot[warp][1] = acc1; }
    __syncthreads();
    if (tid < 4) {
        float d0 = sdot[tid][0] + sdot[tid + 4][0];
        float d1 = sdot[tid][1] + sdot[tid + 4][1];
        int r = rowBase + tid * 2;
        float u0 = __ldg(A + r) / d0;
        float u1 = __ldg(A + r + 1) / d1;
        g_U[r] = u0;
        g_U[r + 1] = u1;
        sUp[tid] = u0 + u1;
    }
    __syncthreads();
    if (tid == 0)
        atomicAdd(&g_usum[slot], (sUp[0] + sUp[1]) + (sUp[2] + sUp[3]));
}

// ---------------------------------------------------------------- slice[it] += Q8^T U; tail -> V_{it+1} (with D corr)
// 1024 blocks: 128 row-chunks x 8 col-chunks; 4 cols/thread; double-buffered rows
__global__ void __launch_bounds__(256) k_colmv8(const float* __restrict__ B, int it) {
    __shared__ float sU[64];
    int tid = threadIdx.x;
    int rb = blockIdx.x >> 3;
    int col0 = (blockIdx.x & 7) * 1024 + tid * 4;
    int row0 = rb * 64;
    if (tid < 64) sU[tid] = g_U[row0 + tid];
    __syncthreads();
    const unsigned int* qp =
        reinterpret_cast<const unsigned int*>(g_Q8 + (size_t)row0 * NN + col0);
    unsigned int w[2][8];
#pragma unroll
    for (int u = 0; u < 8; ++u) w[0][u] = qp[(size_t)u * (NN / 4)];
    float a0 = 0.f, a1 = 0.f, a2 = 0.f, a3 = 0.f;
#pragma unroll
    for (int r = 0; r < 64; r += 8) {
        const int p = (r >> 3) & 1;
        if (r + 8 < 64) {
#pragma unroll
            for (int u = 0; u < 8; ++u) w[p ^ 1][u] = qp[(size_t)(r + 8 + u) * (NN / 4)];
        }
#pragma unroll
        for (int u = 0; u < 8; ++u) {
            float uu = sU[r + u];
            float2 lo = f8x2_to_f2(w[p][u] & 0xffffu);
            float2 hi = f8x2_to_f2(w[p][u] >> 16);
            a0 = fmaf(lo.x, uu, a0);
            a1 = fmaf(lo.y, uu, a1);
            a2 = fmaf(hi.x, uu, a2);
            a3 = fmaf(hi.y, uu, a3);
        }
    }
    float* ca = g_slice[it][rb & 1];
    atomicAdd(&ca[col0 + 0], a0);
    atomicAdd(&ca[col0 + 1], a1);
    atomicAdd(&ca[col0 + 2], a2);
    atomicAdd(&ca[col0 + 3], a3);
    v_finalize_tail(B, it, gridDim.x, 1);
}

// ---------------------------------------------------------------- final: exact Q, fused U10, write T (V10 in g_V)
__global__ void __launch_bounds__(256) k_final(const float* __restrict__ c,
                                               const float* __restrict__ A,
                                               float* __restrict__ out) {
    __shared__ float sV[NN];
    __shared__ float sred[8];
    __shared__ float sbc;
    int tid = threadIdx.x;
    copy_V_smem(sV);
    __syncthreads();
    const float kk = g_kscale;
    for (int row = blockIdx.x; row < NN; row += gridDim.x) {
        const float4* crow = reinterpret_cast<const float4*>(c + (size_t)row * NN);
        float4 qv[8];
        float s = 0.f;
#pragma unroll
        for (int k = 0; k < 8; ++k) {
            int j = tid * 4 + k * 1024;
            float4 v  = crow[tid + k * 256];
            float4 vv = *reinterpret_cast<const float4*>(sV + j);
            float q0 = __expf(-v.x * kk) * vv.x;
            float q1 = __expf(-v.y * kk) * vv.y;
            float q2 = __expf(-v.z * kk) * vv.z;
            float q3 = __expf(-v.w * kk) * vv.w;
            qv[k].x = q0; qv[k].y = q1; qv[k].z = q2; qv[k].w = q3;
            s += (q0 + q1) + (q2 + q3);
        }
        for (int o = 16; o > 0; o >>= 1)
            s += __shfl_down_sync(0xffffffffu, s, o);
        if ((tid & 31) == 0) sred[tid >> 5] = s;
        __syncthreads();
        if (tid < 32) {
            float t = (tid < 8) ? sred[tid] : 0.f;
            for (int o = 4; o > 0; o >>= 1)
                t += __shfl_down_sync(0xffffffffu, t, o);
            if (tid == 0) sbc = __ldg(A + row) / t;
        }
        __syncthreads();
        float scale = sbc;
        float4* orow = reinterpret_cast<float4*>(out + (size_t)row * NN);
#pragma unroll
        for (int k = 0; k < 8; ++k) {
            float4 w = qv[k];
            w.x *= scale; w.y *= scale; w.z *= scale; w.w *= scale;
            orow[tid + k * 256] = w;
        }
        __syncthreads();
    }
}

// ---------------------------------------------------------------- launch
extern "C" void kernel_launch(void* const* d_in, const int* in_sizes, int n_in,
                              void* d_out, int out_size) {
    const float* cdist = (const float*)d_in[0];
    const float* A     = (const float*)d_in[1];
    const float* B     = (const float*)d_in[2];
    float* out = (float*)d_out;

    k_init<<<64, 256>>>();                       // zero slices + D + counters
    k_reduce<<<1184, 256>>>(cdist);              // sum/sumsq + fused kscale
    k_build8<<<dim3(8, 128), 256>>>(cdist, B);   // Q8 + exact colsum + D; tail -> V1
    for (int it = 1; it <= 9; ++it) {
        k_rowmv8<<<1024, 256>>>(A, it);          // U_it = A/(Q8 V); usum[it]
        k_colmv8<<<1024, 256>>>(B, it);          // slice[it] = Q8^T U_it; tail -> V_{it+1} (+corr)
    }
    // U10 fused into output: exact fp32 Q, V10 in g_V, T out
    k_final<<<444, 256>>>(cdist, A, out);
}